// round 4
// baseline (speedup 1.0000x reference)
#include <cuda_runtime.h>

// Depth-5 path signature, B=256, d=10, L=128 (127 segments).
// Output row: [S1(10) | S2(100) | S3(1000) | S4(10000) | S5(100000)] = 111110 floats.
//
// Chen recurrence with rank-1 segment tensors (increment δ):
//   P3[abc] = S3/2 + δc*(S2/6 + δb*(S1/24 + δa/120))
//   Y3[abc] = S3   + δc*(S2/2 + δb*(S1/6  + δa/24))
//   X4[abcd] = S4[abcd] + δd*P3[abc];  S4 += Y3 ⊗ δ;  S5 += X4 ⊗ δ
//   S3 += δc*(S2 + δb*(S1/2 + δa/6));  S2 += δb*(S1 + δa/2);  S1 += δ
//
// CTA = (batch b, a-pair j). 200 threads, thread = one abc (a = 2j + tid/100),
// owning ALL 10 d-columns: 5 packed S4 d-pairs + 50 packed S5 accumulators
// (d-pair x e) in registers. X4/S4 updates are packed over d; S5 updates use a
// broadcast-pair SMEM layout (δe,δe) so no pack MOVs are needed. Private
// register copies of S1/S2/S3 -> zero barriers in the 127-segment loop.

#define NB 256
#define DCH 10
#define LEN 128
#define NSEG 127
#define THREADS 200
#define ROW 111110
#define APAD 12   // sdA row stride: 48B rows, 16B-aligned

typedef unsigned long long ull;

__device__ __forceinline__ ull pk(float lo, float hi) {
    ull r;
    asm("mov.b64 %0, {%1, %2};" : "=l"(r) : "f"(lo), "f"(hi));
    return r;
}
__device__ __forceinline__ void upk(ull v, float& lo, float& hi) {
    asm("mov.b64 {%0, %1}, %2;" : "=f"(lo), "=f"(hi) : "l"(v));
}
__device__ __forceinline__ ull ffma2(ull a, ull b, ull c) {
    ull d;
    asm("fma.rn.f32x2 %0, %1, %2, %3;" : "=l"(d) : "l"(a), "l"(b), "l"(c));
    return d;
}

__global__ __launch_bounds__(THREADS, 2)
void sig_kernel(const float* __restrict__ path, float* __restrict__ out) {
    __shared__ __align__(16) float sdA[NSEG * APAD];  // [t][c] scalar deltas
    __shared__ __align__(16) ull   sdB[NSEG * DCH];   // [t][e] = (δe, δe) broadcast pairs

    const int tid = threadIdx.x;
    const int b   = blockIdx.x / 5;
    const int j   = blockIdx.x % 5;

    // ---- segment increments into both SMEM layouts ----
    const float* pb = path + b * (DCH * LEN);
    for (int idx = tid; idx < NSEG * DCH; idx += THREADS) {
        int c = idx / NSEG, t = idx % NSEG;
        float d = pb[c * LEN + t + 1] - pb[c * LEN + t];
        sdA[t * APAD + c] = d;
        sdB[t * DCH + c]  = pk(d, d);
    }
    __syncthreads();

    const int half = tid / 100;        // a = 2j + half
    const int a    = 2 * j + half;
    const int bc   = tid % 100;
    const int hb   = bc / 10;
    const int hc   = bc % 10;

    float s1 = 0.f, s2 = 0.f, s3 = 0.f;   // private S1[a], S2[ab], S3[abc]
    ull s4p[5];                            // [i] = (S4[abc,2i], S4[abc,2i+1])
    ull s5[5][10];                         // [i][e] = (S5[abc,2i,e], S5[abc,2i+1,e])
#pragma unroll
    for (int i = 0; i < 5; ++i) {
        s4p[i] = 0ull;
#pragma unroll
        for (int e = 0; e < 10; ++e) s5[i][e] = 0ull;
    }

    const float* dl = sdA;
    const ull*   bl = sdB;
    for (int t = 0; t < NSEG; ++t, dl += APAD, bl += DCH) {
        float4 v0 = *(const float4*)dl;        // δ0..δ3
        float4 v1 = *(const float4*)(dl + 4);  // δ4..δ7
        float2 v2 = *(const float2*)(dl + 8);  // δ8, δ9
        float da = dl[a], db = dl[hb], dc = dl[hc];

        // Horner chains (imm-mult FFMA where possible)
        float P1 = fmaf(da, 1.f / 120.f, s1 * (1.f / 24.f));
        float P2 = fmaf(db, P1, s2 * (1.f / 6.f));
        float P3 = fmaf(dc, P2, s3 * 0.5f);
        float Q1 = fmaf(da, 1.f / 24.f, s1 * (1.f / 6.f));
        float Q2 = fmaf(db, Q1, s2 * 0.5f);
        float Y3 = fmaf(dc, Q2, s3);
        float Z1 = fmaf(da, 1.f / 6.f, s1 * 0.5f);
        float Z2 = fmaf(db, Z1, s2);
        s3 = fmaf(dc, Z2, s3);
        float W1 = fmaf(da, 0.5f, s1);
        s2 = fmaf(db, W1, s2);
        s1 += da;

        ull P3p = pk(P3, P3), Y3p = pk(Y3, Y3);
        ull ep[5];                              // d-pairs (δ2i, δ2i+1): reg aliases
        ep[0] = pk(v0.x, v0.y);
        ep[1] = pk(v0.z, v0.w);
        ep[2] = pk(v1.x, v1.y);
        ep[3] = pk(v1.z, v1.w);
        ep[4] = pk(v2.x, v2.y);

        ull Xp[5];
#pragma unroll
        for (int i = 0; i < 5; ++i) {
            Xp[i]  = ffma2(ep[i], P3p, s4p[i]);   // (X4[2i], X4[2i+1])
            s4p[i] = ffma2(ep[i], Y3p, s4p[i]);   // S4 += Y3*δd (packed)
        }
#pragma unroll
        for (int e = 0; e < 10; ++e) {
            ull eb = bl[e];                        // (δe, δe) broadcast LDS.64
#pragma unroll
            for (int i = 0; i < 5; ++i)
                s5[i][e] = ffma2(Xp[i], eb, s5[i][e]);
        }
    }

    // ---- epilogue ----
    float* orow = out + (size_t)b * ROW;
    const int abc = a * 100 + bc;
    if (bc == 0) orow[a] = s1;
    if (hc == 0) orow[10 + a * 10 + hb] = s2;
    orow[110 + abc] = s3;

    // S4: pairs are d-adjacent -> direct STG.64 (1110 + abc*10 is even)
    ull* o4 = (ull*)(orow + 1110 + abc * 10);
#pragma unroll
    for (int i = 0; i < 5; ++i) o4[i] = s4p[i];

    // S5: s5[i][e] lanes map to offsets (2i)*10+e and (2i+1)*10+e in the
    // contiguous 100-float block of this abc. Repack per d-row into e-pairs.
    float* o5 = orow + 11110 + abc * 100;
#pragma unroll
    for (int i = 0; i < 5; ++i) {
        float lo[10], hi[10];
#pragma unroll
        for (int e = 0; e < 10; ++e) upk(s5[i][e], lo[e], hi[e]);
        ull* r0 = (ull*)(o5 + 20 * i);        // row d=2i   (8B-aligned)
        ull* r1 = (ull*)(o5 + 20 * i + 10);   // row d=2i+1
#pragma unroll
        for (int p = 0; p < 5; ++p) {
            r0[p] = pk(lo[2 * p], lo[2 * p + 1]);
            r1[p] = pk(hi[2 * p], hi[2 * p + 1]);
        }
    }
}

extern "C" void kernel_launch(void* const* d_in, const int* in_sizes, int n_in,
                              void* d_out, int out_size) {
    const float* path = (const float*)d_in[0];  // (256, 10, 128) fp32
    float* out = (float*)d_out;                 // (256, 111110) fp32
    sig_kernel<<<NB * 5, THREADS>>>(path, out);
}

// round 6
// speedup vs baseline: 1.4758x; 1.4758x over previous
#include <cuda_runtime.h>

// Depth-5 path signature, B=256, d=10, L=128 (127 segments).
// Output row: [S1(10) | S2(100) | S3(1000) | S4(10000) | S5(100000)] = 111110 floats.
//
// Chen recurrence with rank-1 segment tensors (increment δ):
//   P3[abc] = S3/2 + δc*(S2/6 + δb*(S1/24 + δa/120))
//   Y3[abc] = S3   + δc*(S2/2 + δb*(S1/6  + δa/24))
//   X4[abcd] = S4[abcd] + δd*P3[abc];  S4 += Y3 ⊗ δ;  S5 += X4 ⊗ δ
//   S3 += δc*(S2 + δb*(S1/2 + δa/6));  S2 += δb*(S1 + δa/2);  S1 += δ
//
// CTA = (batch b, a-pair j), 200 threads, thread = one abc (a = 2j + tid/100),
// owning ALL 10 d-columns: 5 packed S4 d-pairs + 50 packed S5 f32x2 accumulators
// in registers. launch_bounds(200,1) -> 255-reg cap so the ~150 live registers
// do NOT spill (R4's regression was the 128-reg cap forcing S5 to local).
// Private register copies of S1/S2/S3 -> zero barriers in the segment loop.

#define NB 256
#define DCH 10
#define LEN 128
#define NSEG 127
#define THREADS 200
#define ROW 111110
#define APAD 12   // sdA row stride: 48B rows, 16B-aligned

typedef unsigned long long ull;

__device__ __forceinline__ ull pk(float lo, float hi) {
    ull r;
    asm("mov.b64 %0, {%1, %2};" : "=l"(r) : "f"(lo), "f"(hi));
    return r;
}
__device__ __forceinline__ void upk(ull v, float& lo, float& hi) {
    asm("mov.b64 {%0, %1}, %2;" : "=f"(lo), "=f"(hi) : "l"(v));
}
__device__ __forceinline__ ull ffma2(ull a, ull b, ull c) {
    ull d;
    asm("fma.rn.f32x2 %0, %1, %2, %3;" : "=l"(d) : "l"(a), "l"(b), "l"(c));
    return d;
}

__global__ __launch_bounds__(THREADS, 1)
void sig_kernel(const float* __restrict__ path, float* __restrict__ out) {
    __shared__ __align__(16) float sdA[NSEG * APAD];  // [t][c] scalar deltas
    __shared__ __align__(16) ull   sdB[NSEG * DCH];   // [t][e] = (δe, δe) broadcast pairs

    const int tid = threadIdx.x;
    const int b   = blockIdx.x / 5;
    const int j   = blockIdx.x % 5;

    // ---- segment increments into both SMEM layouts ----
    const float* pb = path + b * (DCH * LEN);
    for (int idx = tid; idx < NSEG * DCH; idx += THREADS) {
        int c = idx / NSEG, t = idx % NSEG;
        float d = pb[c * LEN + t + 1] - pb[c * LEN + t];
        sdA[t * APAD + c] = d;
        sdB[t * DCH + c]  = pk(d, d);
    }
    __syncthreads();

    const int half = tid / 100;        // a = 2j + half
    const int a    = 2 * j + half;
    const int bc   = tid % 100;
    const int hb   = bc / 10;
    const int hc   = bc % 10;

    float s1 = 0.f, s2 = 0.f, s3 = 0.f;   // private S1[a], S2[ab], S3[abc]
    ull s4p[5];                            // [i] = (S4[abc,2i], S4[abc,2i+1])
    ull s5[5][10];                         // [i][e] = (S5[abc,2i,e], S5[abc,2i+1,e])
#pragma unroll
    for (int i = 0; i < 5; ++i) {
        s4p[i] = 0ull;
#pragma unroll
        for (int e = 0; e < 10; ++e) s5[i][e] = 0ull;
    }

    const float* dl = sdA;
    const ull*   bl = sdB;
    for (int t = 0; t < NSEG; ++t, dl += APAD, bl += DCH) {
        float4 v0 = *(const float4*)dl;        // δ0..δ3
        float4 v1 = *(const float4*)(dl + 4);  // δ4..δ7
        float2 v2 = *(const float2*)(dl + 8);  // δ8, δ9
        float da = dl[a], db = dl[hb], dc = dl[hc];

        // Horner chains
        float P1 = fmaf(da, 1.f / 120.f, s1 * (1.f / 24.f));
        float P2 = fmaf(db, P1, s2 * (1.f / 6.f));
        float P3 = fmaf(dc, P2, s3 * 0.5f);
        float Q1 = fmaf(da, 1.f / 24.f, s1 * (1.f / 6.f));
        float Q2 = fmaf(db, Q1, s2 * 0.5f);
        float Y3 = fmaf(dc, Q2, s3);
        float Z1 = fmaf(da, 1.f / 6.f, s1 * 0.5f);
        float Z2 = fmaf(db, Z1, s2);
        s3 = fmaf(dc, Z2, s3);
        float W1 = fmaf(da, 0.5f, s1);
        s2 = fmaf(db, W1, s2);
        s1 += da;

        ull P3p = pk(P3, P3), Y3p = pk(Y3, Y3);
        ull ep[5];                              // d-pairs (δ2i, δ2i+1)
        ep[0] = pk(v0.x, v0.y);
        ep[1] = pk(v0.z, v0.w);
        ep[2] = pk(v1.x, v1.y);
        ep[3] = pk(v1.z, v1.w);
        ep[4] = pk(v2.x, v2.y);

        ull Xp[5];
#pragma unroll
        for (int i = 0; i < 5; ++i) {
            Xp[i]  = ffma2(ep[i], P3p, s4p[i]);   // (X4[2i], X4[2i+1])
            s4p[i] = ffma2(ep[i], Y3p, s4p[i]);   // S4 += Y3*δd (packed)
        }
#pragma unroll
        for (int e = 0; e < 10; ++e) {
            ull eb = bl[e];                        // (δe, δe) broadcast LDS.64
#pragma unroll
            for (int i = 0; i < 5; ++i)
                s5[i][e] = ffma2(Xp[i], eb, s5[i][e]);
        }
    }

    // ---- epilogue ----
    float* orow = out + (size_t)b * ROW;
    const int abc = a * 100 + bc;
    if (bc == 0) orow[a] = s1;
    if (hc == 0) orow[10 + a * 10 + hb] = s2;
    orow[110 + abc] = s3;

    // S4: pairs are d-adjacent -> direct STG.64 (1110 + abc*10 is even)
    ull* o4 = (ull*)(orow + 1110 + abc * 10);
#pragma unroll
    for (int i = 0; i < 5; ++i) o4[i] = s4p[i];

    // S5: s5[i][e] lanes are rows d=2i and d=2i+1 of this abc's 100-float block.
    float* o5 = orow + 11110 + abc * 100;
#pragma unroll
    for (int i = 0; i < 5; ++i) {
        float lo[10], hi[10];
#pragma unroll
        for (int e = 0; e < 10; ++e) upk(s5[i][e], lo[e], hi[e]);
        ull* r0 = (ull*)(o5 + 20 * i);        // row d=2i   (8B-aligned)
        ull* r1 = (ull*)(o5 + 20 * i + 10);   // row d=2i+1
#pragma unroll
        for (int p = 0; p < 5; ++p) {
            r0[p] = pk(lo[2 * p], lo[2 * p + 1]);
            r1[p] = pk(hi[2 * p], hi[2 * p + 1]);
        }
    }
}

extern "C" void kernel_launch(void* const* d_in, const int* in_sizes, int n_in,
                              void* d_out, int out_size) {
    const float* path = (const float*)d_in[0];  // (256, 10, 128) fp32
    float* out = (float*)d_out;                 // (256, 111110) fp32
    sig_kernel<<<NB * 5, THREADS>>>(path, out);
}

// round 7
// speedup vs baseline: 1.5145x; 1.0262x over previous
#include <cuda_runtime.h>

// Depth-5 path signature, B=256, d=10, L=128 (127 segments).
// Output row: [S1(10) | S2(100) | S3(1000) | S4(10000) | S5(100000)] = 111110 floats.
//
// Chen recurrence with rank-1 segment tensors (increment δ):
//   P3[abc] = S3/2 + δc*(S2/6 + δb*(S1/24 + δa/120))
//   Y3[abc] = S3   + δc*(S2/2 + δb*(S1/6  + δa/24))
//   X4[abcd] = S4[abcd] + δd*P3[abc];  S4 += Y3 ⊗ δ;  S5 += X4 ⊗ δ
//   S3 += δc*(S2 + δb*(S1/2 + δa/6));  S2 += δb*(S1 + δa/2);  S1 += δ
//
// CTA = (batch b, a-pair j), 200 threads, thread = one abc, owns all 10 d:
// 5 packed S4 d-pairs + 50 packed S5 f32x2 accumulators in registers.
// SOFTWARE PIPELINED: segment t+1's LDS + Horner chain run between Xp(t) and
// the 50-ffma2 S5(t) block, hiding LDS latency (29cyc) and the serial Horner
// chain under the high-ILP S5 updates. One zero pad row makes the final
// prefetch benign (zero increment leaves state unchanged).

#define NB 256
#define DCH 10
#define LEN 128
#define NSEG 127
#define THREADS 200
#define ROW 111110
#define APAD 12
#define PADROWS (NSEG + 1)

typedef unsigned long long ull;

__device__ __forceinline__ ull pk(float lo, float hi) {
    ull r;
    asm("mov.b64 %0, {%1, %2};" : "=l"(r) : "f"(lo), "f"(hi));
    return r;
}
__device__ __forceinline__ void upk(ull v, float& lo, float& hi) {
    asm("mov.b64 {%0, %1}, %2;" : "=f"(lo), "=f"(hi) : "l"(v));
}
__device__ __forceinline__ ull ffma2(ull a, ull b, ull c) {
    ull d;
    asm("fma.rn.f32x2 %0, %1, %2, %3;" : "=l"(d) : "l"(a), "l"(b), "l"(c));
    return d;
}

__global__ __launch_bounds__(THREADS, 1)
void sig_kernel(const float* __restrict__ path, float* __restrict__ out) {
    __shared__ __align__(16) float sdA[PADROWS * APAD];  // [t][c] scalar deltas
    __shared__ __align__(16) ull   sdB[PADROWS * DCH];   // [t][e] = (δe, δe) pairs

    const int tid = threadIdx.x;
    const int b   = blockIdx.x / 5;
    const int j   = blockIdx.x % 5;

    // ---- segment increments into both SMEM layouts ----
    const float* pb = path + b * (DCH * LEN);
    for (int idx = tid; idx < NSEG * DCH; idx += THREADS) {
        int c = idx / NSEG, t = idx % NSEG;
        float d = pb[c * LEN + t + 1] - pb[c * LEN + t];
        sdA[t * APAD + c] = d;
        sdB[t * DCH + c]  = pk(d, d);
    }
    if (tid < APAD) sdA[NSEG * APAD + tid] = 0.f;   // zero pad row
    if (tid < DCH)  sdB[NSEG * DCH + tid]  = 0ull;
    __syncthreads();

    const int half = tid / 100;        // a = 2j + half
    const int a    = 2 * j + half;
    const int bc   = tid % 100;
    const int hb   = bc / 10;
    const int hc   = bc % 10;

    float s1 = 0.f, s2 = 0.f, s3 = 0.f;
    ull s4p[5];
    ull s5[5][10];
#pragma unroll
    for (int i = 0; i < 5; ++i) {
        s4p[i] = 0ull;
#pragma unroll
        for (int e = 0; e < 10; ++e) s5[i][e] = 0ull;
    }

    // ---- prologue: segment 0 deltas + Horner(0) + state update(0) ----
    ull ep[5];
#pragma unroll
    for (int i = 0; i < 5; ++i) ep[i] = *(const ull*)(sdA + 2 * i);
    ull P3p, Y3p;
    {
        float da = sdA[a], db = sdA[hb], dc = sdA[hc];
        // initial state is zero: Horner folds to pure increment terms
        float P3 = dc * (db * (da * (1.f / 120.f)) * (1.f / 1.f));
        float P2 = db * (da * (1.f / 120.f));
        P3 = dc * P2;                       // P3 = δaδbδc/120
        float Y3 = dc * (db * (da * (1.f / 24.f)));  // δaδbδc/24
        s3 = dc * (db * (da * (1.f / 6.f)));          // δaδbδc/6
        s2 = db * (da * 0.5f);
        s1 = da;
        P3p = pk(P3, P3);
        Y3p = pk(Y3, Y3);
    }

#pragma unroll 2
    for (int t = 0; t < NSEG; ++t) {
        // (1) X4 / S4 for segment t
        ull Xp[5];
#pragma unroll
        for (int i = 0; i < 5; ++i) {
            Xp[i]  = ffma2(ep[i], P3p, s4p[i]);
            s4p[i] = ffma2(ep[i], Y3p, s4p[i]);
        }

        // (2) prefetch segment t+1 (zero pad row at t=126)
        const float* dn = sdA + (t + 1) * APAD;
#pragma unroll
        for (int i = 0; i < 5; ++i) ep[i] = *(const ull*)(dn + 2 * i);
        float dan = dn[a], dbn = dn[hb], dcn = dn[hc];

        // (3) Horner(t+1) + state update (independent of S5 block below)
        float P1 = fmaf(dan, 1.f / 120.f, s1 * (1.f / 24.f));
        float P2 = fmaf(dbn, P1, s2 * (1.f / 6.f));
        float P3 = fmaf(dcn, P2, s3 * 0.5f);
        float Q1 = fmaf(dan, 1.f / 24.f, s1 * (1.f / 6.f));
        float Q2 = fmaf(dbn, Q1, s2 * 0.5f);
        float Y3 = fmaf(dcn, Q2, s3);
        float Z1 = fmaf(dan, 1.f / 6.f, s1 * 0.5f);
        float Z2 = fmaf(dbn, Z1, s2);
        s3 = fmaf(dcn, Z2, s3);
        float W1 = fmaf(dan, 0.5f, s1);
        s2 = fmaf(dbn, W1, s2);
        s1 += dan;
        P3p = pk(P3, P3);
        Y3p = pk(Y3, Y3);

        // (4) S5 block for segment t (50 independent ffma2)
        const ull* bl = sdB + t * DCH;
#pragma unroll
        for (int e = 0; e < 10; ++e) {
            ull eb = bl[e];
#pragma unroll
            for (int i = 0; i < 5; ++i)
                s5[i][e] = ffma2(Xp[i], eb, s5[i][e]);
        }
    }

    // ---- epilogue ----
    float* orow = out + (size_t)b * ROW;
    const int abc = a * 100 + bc;
    if (bc == 0) orow[a] = s1;
    if (hc == 0) orow[10 + a * 10 + hb] = s2;
    orow[110 + abc] = s3;

    ull* o4 = (ull*)(orow + 1110 + abc * 10);
#pragma unroll
    for (int i = 0; i < 5; ++i) o4[i] = s4p[i];

    float* o5 = orow + 11110 + abc * 100;
#pragma unroll
    for (int i = 0; i < 5; ++i) {
        float lo[10], hi[10];
#pragma unroll
        for (int e = 0; e < 10; ++e) upk(s5[i][e], lo[e], hi[e]);
        ull* r0 = (ull*)(o5 + 20 * i);
        ull* r1 = (ull*)(o5 + 20 * i + 10);
#pragma unroll
        for (int p = 0; p < 5; ++p) {
            r0[p] = pk(lo[2 * p], lo[2 * p + 1]);
            r1[p] = pk(hi[2 * p], hi[2 * p + 1]);
        }
    }
}

extern "C" void kernel_launch(void* const* d_in, const int* in_sizes, int n_in,
                              void* d_out, int out_size) {
    const float* path = (const float*)d_in[0];  // (256, 10, 128) fp32
    float* out = (float*)d_out;                 // (256, 111110) fp32
    sig_kernel<<<NB * 5, THREADS>>>(path, out);
}